// round 1
// baseline (speedup 1.0000x reference)
#include <cuda_runtime.h>
#include <cstddef>

#define H       128
#define NPL     100000
#define NTR     200000
#define NAR     50000
#define NT      350000
#define OFF_TR  100000
#define OFF_AR  300000
#define EPT     500000
#define ETA     200000
#define LBL     100000
#define GRID    152

// ---------------- scratch (no allocations allowed) ----------------
__device__ float g_x  [(size_t)NT * H];   // node features (ping)
__device__ float g_y  [(size_t)NT * H];   // node features (pong)
__device__ float g_agg[(size_t)NT * H];   // neighbor-sum accumulator
__device__ float g_inv[NT];               // 1/max(deg,1)
__device__ int   g_deg[NT];

// ---------------- helpers ----------------
__device__ __forceinline__ float f4c(float4 v, int i) {
    switch (i) { case 0: return v.x; case 1: return v.y; case 2: return v.z; default: return v.w; }
}

__device__ __forceinline__ void red4(float* p, float4 v) {
    asm volatile("red.global.add.v4.f32 [%0], {%1,%2,%3,%4};"
                 :: "l"(p), "f"(v.x), "f"(v.y), "f"(v.z), "f"(v.w) : "memory");
}

// ---------------- embedding gather (pl / ar) ----------------
__global__ void k_embed(const int* __restrict__ ids, const float* __restrict__ table,
                        const float* __restrict__ trow, float* __restrict__ out, int n)
{
    int t = blockIdx.x * blockDim.x + threadIdx.x;
    if (t >= n * 32) return;
    int i = t >> 5, c = t & 31;
    float4 v  = ((const float4*)(table + (size_t)ids[i] * H))[c];
    float4 tv = ((const float4*)trow)[c];
    v.x += tv.x; v.y += tv.y; v.z += tv.z; v.w += tv.w;
    ((float4*)(out + (size_t)i * H))[c] = v;
}

// ---------------- degree count (both directions per undirected edge) ----------------
__global__ void k_deg(const int* __restrict__ sp, const int* __restrict__ dp,
                      const int* __restrict__ st, const int* __restrict__ dt)
{
    int e = blockIdx.x * blockDim.x + threadIdx.x;
    if (e < EPT) {
        int s = sp[e], d = dp[e] + OFF_TR;
        atomicAdd(&g_deg[d], 1);
        atomicAdd(&g_deg[s], 1);
    } else if (e < EPT + ETA) {
        int i = e - EPT;
        int s = st[i] + OFF_TR, d = dt[i] + OFF_AR;
        atomicAdd(&g_deg[d], 1);
        atomicAdd(&g_deg[s], 1);
    }
}

__global__ void k_inv()
{
    int i = blockIdx.x * blockDim.x + threadIdx.x;
    if (i < NT) g_inv[i] = 1.0f / fmaxf((float)g_deg[i], 1.0f);
}

// ---------------- edge scatter: agg[dst] += x[src] (both directions) ----------------
// one warp per undirected edge, lane c owns float4 chunk c
__global__ void k_scatter(const float* __restrict__ x,
                          const int* __restrict__ sp, const int* __restrict__ dp,
                          const int* __restrict__ st, const int* __restrict__ dt)
{
    long long t = (long long)blockIdx.x * blockDim.x + threadIdx.x;
    if (t >= (long long)(EPT + ETA) * 32) return;
    int e = (int)(t >> 5), c = (int)(t & 31);
    int a, b;
    if (e < EPT) { a = sp[e];          b = dp[e] + OFF_TR; }
    else { int i = e - EPT; a = st[i] + OFF_TR; b = dt[i] + OFF_AR; }
    float4 va = ((const float4*)(x + (size_t)a * H))[c];
    float4 vb = ((const float4*)(x + (size_t)b * H))[c];
    red4(g_agg + (size_t)b * H + 4 * c, va);
    red4(g_agg + (size_t)a * H + 4 * c, vb);
}

// ---------------- fused linear:  out = act( A@W1^T * scale? + bias(+bias2) [+ B@W2^T] )
// persistent blocks; W transposed in smem (pad 129 -> conflict-free STS+LDS);
// thread tile: 4 nodes x 4 interleaved cols (jt, jt+32, jt+64, jt+96)
template<bool DUAL, bool RELU, bool SCALE>
__global__ void __launch_bounds__(512, 1) k_linear(
    const float* __restrict__ A, const float* __restrict__ B,
    const float* __restrict__ scale,
    const float* __restrict__ W1, const float* __restrict__ W2,
    const float* __restrict__ b1, const float* __restrict__ b2,
    float* __restrict__ out, int n)
{
    extern __shared__ float sm[];
    float* W1T = sm;                         // 128 x 129 : W1T[k*129+j] = W1[j][k]
    float* W2T = W1T + 16512;
    float* bs  = DUAL ? (W2T + 16512) : W2T; // 128
    float* Ash = bs + 128;                   // 64 x 128
    float* Bsh = Ash + 8192;                 // 64 x 128 (DUAL only)

    const int tid = threadIdx.x;
    for (int idx = tid; idx < 16384; idx += 512) {
        int j = idx >> 7, k = idx & 127;
        W1T[k * 129 + j] = W1[idx];
        if (DUAL) W2T[k * 129 + j] = W2[idx];
    }
    for (int j = tid; j < 128; j += 512)
        bs[j] = b1[j] + (b2 ? b2[j] : 0.0f);
    __syncthreads();

    const int jt = tid & 31;
    const int nt = tid >> 5;     // 0..15
    const int ntiles = (n + 63) >> 6;

    for (int tile = blockIdx.x; tile < ntiles; tile += gridDim.x) {
        const int n0 = tile << 6;
        for (int idx = tid; idx < 8192; idx += 512) {
            int nl = idx >> 7, k = idx & 127;
            int gn = n0 + nl;
            float av = 0.f, bv = 0.f;
            if (gn < n) {
                av = A[(size_t)gn * H + k];
                if (SCALE) av *= scale[gn];
                if (DUAL)  bv = B[(size_t)gn * H + k];
            }
            Ash[idx] = av;
            if (DUAL) Bsh[idx] = bv;
        }
        __syncthreads();

        float acc[4][4];
        #pragma unroll
        for (int i = 0; i < 4; i++)
            #pragma unroll
            for (int c = 0; c < 4; c++) acc[i][c] = bs[jt + 32 * c];

        #pragma unroll 4
        for (int k4 = 0; k4 < 32; k4++) {
            float4 a[4], b[4];
            #pragma unroll
            for (int i = 0; i < 4; i++) {
                a[i] = *(const float4*)(Ash + (nt * 4 + i) * 128 + k4 * 4);
                if (DUAL) b[i] = *(const float4*)(Bsh + (nt * 4 + i) * 128 + k4 * 4);
            }
            #pragma unroll
            for (int kk = 0; kk < 4; kk++) {
                const int k = k4 * 4 + kk;
                float w1[4], w2[4];
                #pragma unroll
                for (int c = 0; c < 4; c++) {
                    w1[c] = W1T[k * 129 + jt + 32 * c];
                    if (DUAL) w2[c] = W2T[k * 129 + jt + 32 * c];
                }
                #pragma unroll
                for (int i = 0; i < 4; i++) {
                    float av = f4c(a[i], kk);
                    float bv = DUAL ? f4c(b[i], kk) : 0.f;
                    #pragma unroll
                    for (int c = 0; c < 4; c++) {
                        acc[i][c] += av * w1[c];
                        if (DUAL) acc[i][c] += bv * w2[c];
                    }
                }
            }
        }

        #pragma unroll
        for (int i = 0; i < 4; i++) {
            int gn = n0 + nt * 4 + i;
            if (gn < n) {
                #pragma unroll
                for (int c = 0; c < 4; c++) {
                    float v = acc[i][c];
                    if (RELU) v = fmaxf(v, 0.f);
                    out[(size_t)gn * H + jt + 32 * c] = v;
                }
            }
        }
        __syncthreads();
    }
}

// ---------------- predictor: logits = Wp2 @ relu(Wp1 @ [pl;tr] + bp1) + bp2
__global__ void __launch_bounds__(512, 1) k_pred(
    const float* __restrict__ xf,
    const int* __restrict__ lrow, const int* __restrict__ lcol,
    const float* __restrict__ Wp1, const float* __restrict__ bp1,
    const float* __restrict__ Wp2, const float* __restrict__ bp2,
    float* __restrict__ out)
{
    extern __shared__ float sm[];
    float* WT   = sm;            // 256 x 129 : WT[k*129+j] = Wp1[j][k]
    float* cT   = WT + 256 * 129;// 256 x 64  : cT[k*64+l] = concat[l][k]
    float* bp1s = cT + 16384;    // 128
    float* wp2s = bp1s + 128;    // 128

    const int tid = threadIdx.x;
    for (int idx = tid; idx < 128 * 256; idx += 512) {
        int j = idx >> 8, k = idx & 255;
        WT[k * 129 + j] = Wp1[idx];
    }
    for (int j = tid; j < 128; j += 512) { bp1s[j] = bp1[j]; wp2s[j] = Wp2[j]; }
    const float bp2v = bp2[0];
    __syncthreads();

    const int jt = tid & 31;
    const int w  = tid >> 5;     // 0..15, warp w owns labels w*4..w*4+3 of the tile
    const int ntiles = (LBL + 63) >> 6;

    for (int tile = blockIdx.x; tile < ntiles; tile += gridDim.x) {
        const int l0 = tile << 6;
        for (int idx = tid; idx < 64 * 256; idx += 512) {
            int l = idx >> 8, k = idx & 255;
            int gl = l0 + l;
            float v = 0.f;
            if (gl < LBL) {
                int row = (k < 128) ? lrow[gl] : (OFF_TR + lcol[gl]);
                v = xf[(size_t)row * H + (k & 127)];
            }
            cT[k * 64 + l] = v;
        }
        __syncthreads();

        float acc[4][4] = {};
        #pragma unroll 4
        for (int k = 0; k < 256; k++) {
            float4 cv = *(const float4*)(cT + k * 64 + w * 4);
            float wv[4];
            #pragma unroll
            for (int c = 0; c < 4; c++) wv[c] = WT[k * 129 + jt + 32 * c];
            #pragma unroll
            for (int l = 0; l < 4; l++) {
                float cl = f4c(cv, l);
                #pragma unroll
                for (int c = 0; c < 4; c++) acc[l][c] += cl * wv[c];
            }
        }

        #pragma unroll
        for (int l = 0; l < 4; l++) {
            float p = 0.f;
            #pragma unroll
            for (int c = 0; c < 4; c++) {
                float h = fmaxf(acc[l][c] + bp1s[jt + 32 * c], 0.f);
                p += h * wp2s[jt + 32 * c];
            }
            #pragma unroll
            for (int off = 16; off > 0; off >>= 1)
                p += __shfl_xor_sync(0xffffffffu, p, off);
            int gl = l0 + w * 4 + l;
            if (jt == 0 && gl < LBL) out[gl] = p + bp2v;
        }
        __syncthreads();
    }
}

// ---------------- launch ----------------
extern "C" void kernel_launch(void* const* d_in, const int* in_sizes, int n_in,
                              void* d_out, int out_size)
{
    const int*   pl_ids   = (const int*)  d_in[0];
    const int*   ar_ids   = (const int*)  d_in[1];
    const float* track_x  = (const float*)d_in[2];
    const int*   src_pt   = (const int*)  d_in[3];
    const int*   dst_pt   = (const int*)  d_in[4];
    const int*   src_ta   = (const int*)  d_in[5];
    const int*   dst_ta   = (const int*)  d_in[6];
    const int*   lab_row  = (const int*)  d_in[7];
    const int*   lab_col  = (const int*)  d_in[8];
    const float* pl_table = (const float*)d_in[9];
    const float* ar_table = (const float*)d_in[10];
    const float* Wtr      = (const float*)d_in[11];
    const float* btr      = (const float*)d_in[12];
    const float* type_tab = (const float*)d_in[13];
    const float* Wl0      = (const float*)d_in[14];
    const float* bl0      = (const float*)d_in[15];
    const float* Wr0      = (const float*)d_in[16];
    const float* Wl1      = (const float*)d_in[17];
    const float* bl1      = (const float*)d_in[18];
    const float* Wr1      = (const float*)d_in[19];
    const float* Wp1      = (const float*)d_in[20];
    const float* bp1      = (const float*)d_in[21];
    const float* Wp2      = (const float*)d_in[22];
    const float* bp2      = (const float*)d_in[23];
    float* out = (float*)d_out;

    float *x, *y, *agg, *inv; int* deg;
    cudaGetSymbolAddress((void**)&x,   g_x);
    cudaGetSymbolAddress((void**)&y,   g_y);
    cudaGetSymbolAddress((void**)&agg, g_agg);
    cudaGetSymbolAddress((void**)&inv, g_inv);
    cudaGetSymbolAddress((void**)&deg, g_deg);

    const int SMEM_DUAL   = (2 * 16512 + 128 + 2 * 8192) * 4;    // 198144
    const int SMEM_SINGLE = (16512 + 128 + 8192) * 4;            // 99328
    const int SMEM_PRED   = (256 * 129 + 16384 + 256) * 4;       // 198656

    cudaFuncSetAttribute(k_linear<true,  true,  true >, cudaFuncAttributeMaxDynamicSharedMemorySize, SMEM_DUAL);
    cudaFuncSetAttribute(k_linear<false, false, false>, cudaFuncAttributeMaxDynamicSharedMemorySize, SMEM_SINGLE);
    cudaFuncSetAttribute(k_pred, cudaFuncAttributeMaxDynamicSharedMemorySize, SMEM_PRED);

    // ---- encode ----
    k_embed<<<(NPL * 32 + 255) / 256, 256>>>(pl_ids, pl_table, type_tab, x, NPL);
    k_embed<<<(NAR * 32 + 255) / 256, 256>>>(ar_ids, ar_table, type_tab + 2 * H,
                                             x + (size_t)OFF_AR * H, NAR);
    k_linear<false, false, false><<<GRID, 512, SMEM_SINGLE>>>(
        track_x, nullptr, nullptr, Wtr, nullptr, btr, type_tab + H,
        x + (size_t)OFF_TR * H, NTR);

    // ---- degrees (edges fixed across layers) ----
    cudaMemsetAsync(deg, 0, (size_t)NT * sizeof(int));
    k_deg<<<(EPT + ETA + 255) / 256, 256>>>(src_pt, dst_pt, src_ta, dst_ta);
    k_inv<<<(NT + 255) / 256, 256>>>();

    const long long sc_threads = (long long)(EPT + ETA) * 32;
    const int sc_blocks = (int)((sc_threads + 255) / 256);

    // ---- layer 0 ----
    cudaMemsetAsync(agg, 0, (size_t)NT * H * sizeof(float));
    k_scatter<<<sc_blocks, 256>>>(x, src_pt, dst_pt, src_ta, dst_ta);
    k_linear<true, true, true><<<GRID, 512, SMEM_DUAL>>>(
        agg, x, inv, Wl0, Wr0, bl0, nullptr, y, NT);

    // ---- layer 1 ----
    cudaMemsetAsync(agg, 0, (size_t)NT * H * sizeof(float));
    k_scatter<<<sc_blocks, 256>>>(y, src_pt, dst_pt, src_ta, dst_ta);
    k_linear<true, true, true><<<GRID, 512, SMEM_DUAL>>>(
        agg, y, inv, Wl1, Wr1, bl1, nullptr, x, NT);

    // ---- predictor ----
    k_pred<<<GRID, 512, SMEM_PRED>>>(x, lab_row, lab_col, Wp1, bp1, Wp2, bp2, out);
}

// round 2
// speedup vs baseline: 1.1315x; 1.1315x over previous
#include <cuda_runtime.h>
#include <cstddef>

#define H       128
#define NPL     100000
#define NTR     200000
#define NAR     50000
#define NT      350000
#define OFF_TR  100000
#define OFF_AR  300000
#define EPT     500000
#define ETA     200000
#define LBL     100000
#define GRID    152

// ---------------- scratch (no allocations allowed) ----------------
__device__ float g_x  [(size_t)NT * H];   // node features (ping)
__device__ float g_y  [(size_t)NT * H];   // node features (pong) / concat scratch
__device__ float g_agg[(size_t)NT * H];   // neighbor-sum accumulator / h scratch
__device__ float g_inv[NT];               // 1/max(deg,1)
__device__ int   g_deg[NT];

// ---------------- helpers ----------------
__device__ __forceinline__ void fma2(unsigned long long& d,
                                     unsigned long long a, unsigned long long b) {
    asm("fma.rn.f32x2 %0, %1, %2, %0;" : "+l"(d) : "l"(a), "l"(b));
}

union U64F2 { unsigned long long u; float2 f; };

__device__ __forceinline__ void red4(float* p, float4 v) {
    asm volatile("red.global.add.v4.f32 [%0], {%1,%2,%3,%4};"
                 :: "l"(p), "f"(v.x), "f"(v.y), "f"(v.z), "f"(v.w) : "memory");
}

// ---------------- embedding gather (pl / ar) ----------------
__global__ void k_embed(const int* __restrict__ ids, const float* __restrict__ table,
                        const float* __restrict__ trow, float* __restrict__ out, int n)
{
    int t = blockIdx.x * blockDim.x + threadIdx.x;
    if (t >= n * 32) return;
    int i = t >> 5, c = t & 31;
    float4 v  = ((const float4*)(table + (size_t)ids[i] * H))[c];
    float4 tv = ((const float4*)trow)[c];
    v.x += tv.x; v.y += tv.y; v.z += tv.z; v.w += tv.w;
    ((float4*)(out + (size_t)i * H))[c] = v;
}

// ---------------- degree count ----------------
__global__ void k_deg(const int* __restrict__ sp, const int* __restrict__ dp,
                      const int* __restrict__ st, const int* __restrict__ dt)
{
    int e = blockIdx.x * blockDim.x + threadIdx.x;
    if (e < EPT) {
        int s = sp[e], d = dp[e] + OFF_TR;
        atomicAdd(&g_deg[d], 1);
        atomicAdd(&g_deg[s], 1);
    } else if (e < EPT + ETA) {
        int i = e - EPT;
        int s = st[i] + OFF_TR, d = dt[i] + OFF_AR;
        atomicAdd(&g_deg[d], 1);
        atomicAdd(&g_deg[s], 1);
    }
}

__global__ void k_inv()
{
    int i = blockIdx.x * blockDim.x + threadIdx.x;
    if (i < NT) g_inv[i] = 1.0f / fmaxf((float)g_deg[i], 1.0f);
}

// ---------------- edge scatter: agg[dst] += x[src] (both directions) ----------------
__global__ void k_scatter(const float* __restrict__ x,
                          const int* __restrict__ sp, const int* __restrict__ dp,
                          const int* __restrict__ st, const int* __restrict__ dt)
{
    long long t = (long long)blockIdx.x * blockDim.x + threadIdx.x;
    if (t >= (long long)(EPT + ETA) * 32) return;
    int e = (int)(t >> 5), c = (int)(t & 31);
    int a, b;
    if (e < EPT) { a = sp[e];          b = dp[e] + OFF_TR; }
    else { int i = e - EPT; a = st[i] + OFF_TR; b = dt[i] + OFF_AR; }
    float4 va = ((const float4*)(x + (size_t)a * H))[c];
    float4 vb = ((const float4*)(x + (size_t)b * H))[c];
    red4(g_agg + (size_t)b * H + 4 * c, va);
    red4(g_agg + (size_t)a * H + 4 * c, vb);
}

// ---------------- f32x2 fused linear ----------------
// out[n][128] = act( concatK(A[,scale],B) @ [W1;W2]^T + b1(+b2) )
// K pairs packed into f32x2 lanes: acc = (even-k partial, odd-k partial).
// smem: W'[k2][c] = float2(W[c][2k2], W[c][2k2+1]) ; Ash[64][KK] staged fp32.
// 512 thr: warp w owns nodes w*4..w*4+3 (A reads broadcast);
// lane jt owns cols {2jt,2jt+1,64+2jt,65+2jt} (conflict-free LDS.128 on W').
template<int KK, bool DUAL, bool RELU, bool SCALE>
__global__ void __launch_bounds__(512, 1) k_linear(
    const float* __restrict__ A, const float* __restrict__ B,
    const float* __restrict__ scale,
    const float* __restrict__ W1, const float* __restrict__ W2,
    const float* __restrict__ b1, const float* __restrict__ b2,
    float* __restrict__ out, int n)
{
    extern __shared__ float sm[];
    float2* Wp = (float2*)sm;                 // (KK/2) x 128 float2
    float*  Ash = sm + KK * 128;              // 64 x KK
    float*  bs  = Ash + 64 * KK;              // 128

    const int tid = threadIdx.x;

    // stage packed W'
    for (int idx = tid; idx < (KK / 2) * 128; idx += 512) {
        int k2 = idx >> 7, c = idx & 127;
        const float* src;
        if (DUAL) src = (k2 < 64) ? (W1 + c * 128 + 2 * k2)
                                  : (W2 + c * 128 + 2 * (k2 - 64));
        else      src = W1 + c * KK + 2 * k2;
        Wp[idx] = *(const float2*)src;
    }
    for (int j = tid; j < 128; j += 512)
        bs[j] = b1[j] + (b2 ? b2[j] : 0.0f);
    __syncthreads();

    const int jt = tid & 31;
    const int w  = tid >> 5;            // 0..15
    const int ntiles = (n + 63) >> 6;

    for (int tile = blockIdx.x; tile < ntiles; tile += gridDim.x) {
        const int n0 = tile << 6;
        // stage A (and B) into Ash[node][KK]
        for (int idx = tid; idx < 64 * (KK / 4); idx += 512) {
            int node = idx / (KK / 4), kc = idx % (KK / 4);
            int gn = n0 + node;
            float4 v = make_float4(0.f, 0.f, 0.f, 0.f);
            if (gn < n) {
                if (DUAL) {
                    if (kc < 32) {
                        v = ((const float4*)(A + (size_t)gn * 128))[kc];
                        float s = scale[gn];
                        v.x *= s; v.y *= s; v.z *= s; v.w *= s;
                    } else {
                        v = ((const float4*)(B + (size_t)gn * 128))[kc - 32];
                    }
                } else {
                    v = ((const float4*)(A + (size_t)gn * KK))[kc];
                    if (SCALE) {
                        float s = scale[gn];
                        v.x *= s; v.y *= s; v.z *= s; v.w *= s;
                    }
                }
            }
            *(float4*)(Ash + node * KK + kc * 4) = v;
        }
        __syncthreads();

        unsigned long long acc[4][4];
        #pragma unroll
        for (int i = 0; i < 4; i++)
            #pragma unroll
            for (int c = 0; c < 4; c++) acc[i][c] = 0ull;

        const float* AshW = Ash + (w * 4) * KK;

        #pragma unroll 2
        for (int k4 = 0; k4 < KK / 4; k4++) {
            ulonglong2 a0 = *(const ulonglong2*)(AshW + 0 * KK + k4 * 4);
            ulonglong2 a1 = *(const ulonglong2*)(AshW + 1 * KK + k4 * 4);
            ulonglong2 a2 = *(const ulonglong2*)(AshW + 2 * KK + k4 * 4);
            ulonglong2 a3 = *(const ulonglong2*)(AshW + 3 * KK + k4 * 4);
            const float2* wr = Wp + (size_t)(2 * k4) * 128;
            ulonglong2 wA0 = *(const ulonglong2*)(wr + 2 * jt);
            ulonglong2 wA1 = *(const ulonglong2*)(wr + 64 + 2 * jt);
            ulonglong2 wB0 = *(const ulonglong2*)(wr + 128 + 2 * jt);
            ulonglong2 wB1 = *(const ulonglong2*)(wr + 192 + 2 * jt);

            #define ROW(i, ai)                                            \
                fma2(acc[i][0], ai.x, wA0.x); fma2(acc[i][1], ai.x, wA0.y); \
                fma2(acc[i][2], ai.x, wA1.x); fma2(acc[i][3], ai.x, wA1.y); \
                fma2(acc[i][0], ai.y, wB0.x); fma2(acc[i][1], ai.y, wB0.y); \
                fma2(acc[i][2], ai.y, wB1.x); fma2(acc[i][3], ai.y, wB1.y);
            ROW(0, a0) ROW(1, a1) ROW(2, a2) ROW(3, a3)
            #undef ROW
        }

        #pragma unroll
        for (int i = 0; i < 4; i++) {
            int gn = n0 + w * 4 + i;
            if (gn < n) {
                float v[4];
                #pragma unroll
                for (int c = 0; c < 4; c++) {
                    U64F2 t; t.u = acc[i][c];
                    v[c] = t.f.x + t.f.y;
                }
                v[0] += bs[2 * jt];      v[1] += bs[2 * jt + 1];
                v[2] += bs[64 + 2 * jt]; v[3] += bs[65 + 2 * jt];
                if (RELU) {
                    v[0] = fmaxf(v[0], 0.f); v[1] = fmaxf(v[1], 0.f);
                    v[2] = fmaxf(v[2], 0.f); v[3] = fmaxf(v[3], 0.f);
                }
                *(float2*)(out + (size_t)gn * 128 + 2 * jt)      = make_float2(v[0], v[1]);
                *(float2*)(out + (size_t)gn * 128 + 64 + 2 * jt) = make_float2(v[2], v[3]);
            }
        }
        __syncthreads();
    }
}

// ---------------- predictor pieces ----------------
__global__ void k_gather(const float* __restrict__ x,
                         const int* __restrict__ lrow, const int* __restrict__ lcol,
                         float* __restrict__ cat)
{
    long long t = (long long)blockIdx.x * blockDim.x + threadIdx.x;
    if (t >= (long long)LBL * 64) return;
    int l = (int)(t >> 6), c = (int)(t & 63);
    int row = (c < 32) ? lrow[l] : (OFF_TR + lcol[l]);
    float4 v = ((const float4*)(x + (size_t)row * H))[c & 31];
    ((float4*)(cat + (size_t)l * 256))[c] = v;
}

__global__ void k_dot(const float* __restrict__ h,
                      const float* __restrict__ Wp2, const float* __restrict__ bp2,
                      float* __restrict__ out)
{
    long long t = (long long)blockIdx.x * blockDim.x + threadIdx.x;
    if (t >= (long long)LBL * 32) return;
    int l = (int)(t >> 5), c = (int)(t & 31);
    float4 hv = ((const float4*)(h + (size_t)l * H))[c];
    float4 wv = ((const float4*)Wp2)[c];
    float p = hv.x * wv.x + hv.y * wv.y + hv.z * wv.z + hv.w * wv.w;
    #pragma unroll
    for (int off = 16; off > 0; off >>= 1)
        p += __shfl_xor_sync(0xffffffffu, p, off);
    if (c == 0) out[l] = p + bp2[0];
}

// ---------------- launch ----------------
extern "C" void kernel_launch(void* const* d_in, const int* in_sizes, int n_in,
                              void* d_out, int out_size)
{
    const int*   pl_ids   = (const int*)  d_in[0];
    const int*   ar_ids   = (const int*)  d_in[1];
    const float* track_x  = (const float*)d_in[2];
    const int*   src_pt   = (const int*)  d_in[3];
    const int*   dst_pt   = (const int*)  d_in[4];
    const int*   src_ta   = (const int*)  d_in[5];
    const int*   dst_ta   = (const int*)  d_in[6];
    const int*   lab_row  = (const int*)  d_in[7];
    const int*   lab_col  = (const int*)  d_in[8];
    const float* pl_table = (const float*)d_in[9];
    const float* ar_table = (const float*)d_in[10];
    const float* Wtr      = (const float*)d_in[11];
    const float* btr      = (const float*)d_in[12];
    const float* type_tab = (const float*)d_in[13];
    const float* Wl0      = (const float*)d_in[14];
    const float* bl0      = (const float*)d_in[15];
    const float* Wr0      = (const float*)d_in[16];
    const float* Wl1      = (const float*)d_in[17];
    const float* bl1      = (const float*)d_in[18];
    const float* Wr1      = (const float*)d_in[19];
    const float* Wp1      = (const float*)d_in[20];
    const float* bp1      = (const float*)d_in[21];
    const float* Wp2      = (const float*)d_in[22];
    const float* bp2      = (const float*)d_in[23];
    float* out = (float*)d_out;

    float *x, *y, *agg, *inv; int* deg;
    cudaGetSymbolAddress((void**)&x,   g_x);
    cudaGetSymbolAddress((void**)&y,   g_y);
    cudaGetSymbolAddress((void**)&agg, g_agg);
    cudaGetSymbolAddress((void**)&inv, g_inv);
    cudaGetSymbolAddress((void**)&deg, g_deg);

    const int SMEM_256 = (256 * 128 + 64 * 256 + 128) * 4;   // 197120
    const int SMEM_128 = (128 * 128 + 64 * 128 + 128) * 4;   // 98816

    cudaFuncSetAttribute(k_linear<256, true,  true,  true >, cudaFuncAttributeMaxDynamicSharedMemorySize, SMEM_256);
    cudaFuncSetAttribute(k_linear<256, false, true,  false>, cudaFuncAttributeMaxDynamicSharedMemorySize, SMEM_256);
    cudaFuncSetAttribute(k_linear<128, false, false, false>, cudaFuncAttributeMaxDynamicSharedMemorySize, SMEM_128);

    // ---- encode ----
    k_embed<<<(NPL * 32 + 255) / 256, 256>>>(pl_ids, pl_table, type_tab, x, NPL);
    k_embed<<<(NAR * 32 + 255) / 256, 256>>>(ar_ids, ar_table, type_tab + 2 * H,
                                             x + (size_t)OFF_AR * H, NAR);
    k_linear<128, false, false, false><<<GRID, 512, SMEM_128>>>(
        track_x, nullptr, nullptr, Wtr, nullptr, btr, type_tab + H,
        x + (size_t)OFF_TR * H, NTR);

    // ---- degrees ----
    cudaMemsetAsync(deg, 0, (size_t)NT * sizeof(int));
    k_deg<<<(EPT + ETA + 255) / 256, 256>>>(src_pt, dst_pt, src_ta, dst_ta);
    k_inv<<<(NT + 255) / 256, 256>>>();

    const long long sc_threads = (long long)(EPT + ETA) * 32;
    const int sc_blocks = (int)((sc_threads + 255) / 256);

    // ---- layer 0 ----
    cudaMemsetAsync(agg, 0, (size_t)NT * H * sizeof(float));
    k_scatter<<<sc_blocks, 256>>>(x, src_pt, dst_pt, src_ta, dst_ta);
    k_linear<256, true, true, true><<<GRID, 512, SMEM_256>>>(
        agg, x, inv, Wl0, Wr0, bl0, nullptr, y, NT);

    // ---- layer 1 ----
    cudaMemsetAsync(agg, 0, (size_t)NT * H * sizeof(float));
    k_scatter<<<sc_blocks, 256>>>(y, src_pt, dst_pt, src_ta, dst_ta);
    k_linear<256, true, true, true><<<GRID, 512, SMEM_256>>>(
        agg, y, inv, Wl1, Wr1, bl1, nullptr, x, NT);

    // ---- predictor ----
    k_gather<<<(int)(((long long)LBL * 64 + 255) / 256), 256>>>(x, lab_row, lab_col, y);
    k_linear<256, false, true, false><<<GRID, 512, SMEM_256>>>(
        y, nullptr, nullptr, Wp1, nullptr, bp1, nullptr, agg, LBL);
    k_dot<<<(int)(((long long)LBL * 32 + 255) / 256), 256>>>(agg, Wp2, bp2, out);
}